// round 16
// baseline (speedup 1.0000x reference)
#include <cuda_runtime.h>
#include <cuda_fp16.h>
#include <math.h>
#include <stdint.h>

// Problem dims
#define BB   128
#define SS   64
#define DD   1024
#define HH   16
#define HD   64
#define FFN_ 4096
#define MM   (BB*SS)   // 8192 tokens
#define MHALF (MM/2)   // 4096 rows per half-pipeline
#define BHALF (BB/2)

// ---------------- scratch (device globals; no allocation allowed) ------------
__device__ __align__(128) __half g_qkvh[(size_t)MM * 3 * DD];  // [M, 3D] fp16
__device__ __align__(128) float g_res1[(size_t)MM * DD];
__device__ __align__(128) float g_ln1[(size_t)MM * DD];
__device__ __align__(128) float g_res2[(size_t)MM * DD];

// packed fp16 operand buffers: layout [ki][row][64] halves, swizzle baked in
__device__ __align__(128) __half g_xpk[(size_t)MM * DD];
__device__ __align__(128) __half g_wipk[(size_t)3 * DD * DD];
__device__ __align__(128) __half g_wopk[(size_t)DD * DD];
__device__ __align__(128) __half g_w1pk[(size_t)FFN_ * DD];
__device__ __align__(128) __half g_w2pk[(size_t)DD * FFN_];
__device__ __align__(128) __half g_cpk[(size_t)MM * DD];
__device__ __align__(128) __half g_l1pk[(size_t)MM * DD];
__device__ __align__(128) __half g_hpk[(size_t)MM * FFN_];

// ---------------- stream pack: created ONCE at static init (pre-main, pre-baseline)
struct StreamPack {
    cudaStream_t s0, s1;
    cudaEvent_t  eW, eW2, eJ0, eJ1;
    bool ok;
    StreamPack() : s0(0), s1(0), eW(0), eW2(0), eJ0(0), eJ1(0), ok(false) {
        ok = cudaStreamCreateWithFlags(&s0, cudaStreamNonBlocking) == cudaSuccess &&
             cudaStreamCreateWithFlags(&s1, cudaStreamNonBlocking) == cudaSuccess &&
             cudaEventCreateWithFlags(&eW,  cudaEventDisableTiming) == cudaSuccess &&
             cudaEventCreateWithFlags(&eW2, cudaEventDisableTiming) == cudaSuccess &&
             cudaEventCreateWithFlags(&eJ0, cudaEventDisableTiming) == cudaSuccess &&
             cudaEventCreateWithFlags(&eJ1, cudaEventDisableTiming) == cudaSuccess;
        if (!ok) { s0 = 0; s1 = 0; }
    }
};
static StreamPack g_sp;   // constructed at load time, before main()

// ---------------- helpers ------------------------------------------------------
__device__ __forceinline__ uint32_t smem_u32(const void* p) {
    return (uint32_t)__cvta_generic_to_shared(p);
}

__device__ __forceinline__ void ldsm4(uint32_t* r, uint32_t addr) {
    asm volatile("ldmatrix.sync.aligned.m8n8.x4.shared.b16 {%0,%1,%2,%3}, [%4];\n"
                 : "=r"(r[0]), "=r"(r[1]), "=r"(r[2]), "=r"(r[3]) : "r"(addr));
}

__device__ __forceinline__ void mma_f16(float* d, const uint32_t* a, const uint32_t* b) {
    asm volatile(
        "mma.sync.aligned.m16n8k16.row.col.f32.f16.f16.f32 "
        "{%0,%1,%2,%3}, {%4,%5,%6,%7}, {%8,%9}, {%0,%1,%2,%3};\n"
        : "+f"(d[0]), "+f"(d[1]), "+f"(d[2]), "+f"(d[3])
        : "r"(a[0]), "r"(a[1]), "r"(a[2]), "r"(a[3]), "r"(b[0]), "r"(b[1]));
}

__device__ __forceinline__ void mbar_init(uint32_t mbar, uint32_t cnt) {
    asm volatile("mbarrier.init.shared.b64 [%0], %1;" :: "r"(mbar), "r"(cnt) : "memory");
}
__device__ __forceinline__ void mbar_expect_tx(uint32_t mbar, uint32_t bytes) {
    asm volatile("mbarrier.arrive.expect_tx.shared.b64 _, [%0], %1;"
                 :: "r"(mbar), "r"(bytes) : "memory");
}
__device__ __forceinline__ void mbar_arrive(uint32_t mbar) {
    asm volatile("mbarrier.arrive.shared.b64 _, [%0];" :: "r"(mbar) : "memory");
}
__device__ __forceinline__ void mbar_wait(uint32_t mbar, uint32_t parity) {
    asm volatile(
        "{\n\t.reg .pred P1;\n\t"
        "WL_%=:\n\t"
        "mbarrier.try_wait.parity.acquire.cta.shared::cta.b64 P1, [%0], %1, 0x989680;\n\t"
        "@P1 bra.uni WD_%=;\n\t"
        "bra.uni WL_%=;\n\t"
        "WD_%=:\n\t}"
        :: "r"(mbar), "r"(parity) : "memory");
}
__device__ __forceinline__ void bulk_g2s(uint32_t dst, const void* src, uint32_t bytes, uint32_t mbar) {
    asm volatile(
        "cp.async.bulk.shared::cluster.global.mbarrier::complete_tx::bytes [%0], [%1], %2, [%3];"
        :: "r"(dst), "l"(src), "r"(bytes), "r"(mbar) : "memory");
}

__device__ __forceinline__ uint32_t pack_h2(__half a, __half b) {
    return ((uint32_t)*(uint16_t*)&b << 16) | (uint32_t)*(uint16_t*)&a;
}
__device__ __forceinline__ uint32_t hi_pair(float a, float b) {
    return pack_h2(__float2half_rn(a), __float2half_rn(b));
}

// packed index: matrix [R rows, K cols] fp16 -> [ki][row][64] with unit swizzle
__device__ __forceinline__ size_t packed_idx(int row, int col, int R) {
    int kc = (col >> 3) & 7;
    return (((size_t)(col >> 6) * (size_t)R + (size_t)row) << 6)
         + (size_t)(((kc ^ (row & 7)) << 3) + (col & 7));
}

// ---------------- bulk-async fp16 GEMM, full/empty mbarrier pipeline -----------
// MODE 0: C = acc + bias (fp32); MODE 1: + resid (fp32); MODE 2: gelu -> packed
// fp16 (Oh); MODE 3: acc + bias -> plain fp16 row-major (Oh).
// CTA tile 256(M)x128(N), KC=64, 512 threads (16 warps 4x4, warp tile 64x32),
// 4-stage ring. Halves weight-panel L2 traffic vs 128x128.
#define A_BYTES 32768                 // 256 rows x 128B
#define B_BYTES 16384                 // 128 rows x 128B
#define STAGE   (A_BYTES + B_BYTES)   // 49152
#define NSTAGE 4
#define GEMM_SMEM (NSTAGE * STAGE)    // 196608
#define NWARPS 16

template <int MODE>
__global__ void __launch_bounds__(512, 1)
tcgemm(const __half* __restrict__ Apk, const __half* __restrict__ Bpk,
       const float* __restrict__ bias, const float* __restrict__ resid,
       float* __restrict__ C, __half* __restrict__ Oh,
       int M, int N, int K, int mo)
{
    extern __shared__ __align__(128) char smem[];
    __shared__ __align__(8) uint64_t full_s[NSTAGE];
    __shared__ __align__(8) uint64_t empty_s[NSTAGE];
    const uint32_t sb = smem_u32(smem);
    const uint32_t fb = smem_u32(full_s);
    const uint32_t eb = smem_u32(empty_s);

    const int tid  = threadIdx.x;
    const int wid  = tid >> 5;
    const int lane = tid & 31;
    const int wm   = wid >> 2;        // 0..3 (64 rows each)
    const int wn   = wid & 3;         // 0..3 (32 cols each)
    const int bn   = blockIdx.x * 128;
    const int bm   = mo + blockIdx.y * 256;
    const int T    = K >> 6;
    const bool producer = (wid == NWARPS - 1) && (lane == 0);

    float acc[4][4][4];
#pragma unroll
    for (int i = 0; i < 4; i++)
#pragma unroll
        for (int j = 0; j < 4; j++)
#pragma unroll
            for (int f = 0; f < 4; f++) acc[i][j][f] = 0.f;

    if (tid == 0) {
#pragma unroll
        for (int s = 0; s < NSTAGE; s++) {
            mbar_init(fb + 8 * s, 1);
            mbar_init(eb + 8 * s, NWARPS);
        }
        asm volatile("fence.proxy.async.shared::cta;" ::: "memory");
    }
    __syncthreads();

    if (producer) {
#pragma unroll
        for (int s = 0; s < NSTAGE; s++) {
            mbar_expect_tx(fb + 8 * s, STAGE);
            bulk_g2s(sb + s * STAGE,           Apk + (((size_t)s * M + bm) << 6), A_BYTES, fb + 8 * s);
            bulk_g2s(sb + s * STAGE + A_BYTES, Bpk + (((size_t)s * N + bn) << 6), B_BYTES, fb + 8 * s);
        }
    }

    const int a_r  = lane & 15;
    const int a_u  = lane >> 4;
    const int b_rr = lane & 7;
    const int b_nn = (lane >> 4) & 1;
    const int b_u  = (lane >> 3) & 1;

    int slot = 0;
    uint32_t ph = 0;
    for (int t = 0; t < T; ++t) {
        mbar_wait(fb + 8 * slot, ph);
        const uint32_t stA = sb + slot * STAGE;
        const uint32_t stB = stA + A_BYTES;
#pragma unroll
        for (int ks = 0; ks < 4; ks++) {
            uint32_t ah[4][4];
#pragma unroll
            for (int mi = 0; mi < 4; mi++) {
                int r = wm * 64 + mi * 16 + a_r;
                int u = ks * 2 + a_u;
                ldsm4(ah[mi], stA + (uint32_t)(r * 128 + ((u ^ (r & 7)) << 4)));
            }
#pragma unroll
            for (int jp = 0; jp < 2; jp++) {
                int r = wn * 32 + jp * 16 + b_nn * 8 + b_rr;
                int u = ks * 2 + b_u;
                uint32_t bf[4];
                ldsm4(bf, stB + (uint32_t)(r * 128 + ((u ^ (r & 7)) << 4)));
#pragma unroll
                for (int mi = 0; mi < 4; mi++) {
                    mma_f16(acc[mi][2 * jp],     ah[mi], bf);
                    mma_f16(acc[mi][2 * jp + 1], ah[mi], bf + 2);
                }
            }
        }
        if (lane == 0) mbar_arrive(eb + 8 * slot);
        if (producer && t + NSTAGE < T) {
            mbar_wait(eb + 8 * slot, ph);
            const int kk = t + NSTAGE;
            mbar_expect_tx(fb + 8 * slot, STAGE);
            bulk_g2s(sb + slot * STAGE,           Apk + (((size_t)kk * M + bm) << 6), A_BYTES, fb + 8 * slot);
            bulk_g2s(sb + slot * STAGE + A_BYTES, Bpk + (((size_t)kk * N + bn) << 6), B_BYTES, fb + 8 * slot);
        }
        if (++slot == NSTAGE) { slot = 0; ph ^= 1; }
    }

    // ---------------- epilogue (register-only) --------------------------------
    const int trow = lane >> 2;
    const int tcol = (lane & 3) * 2;
#pragma unroll
    for (int mi = 0; mi < 4; mi++) {
#pragma unroll
        for (int half = 0; half < 2; half++) {
            const int row = bm + wm * 64 + mi * 16 + trow + half * 8;
#pragma unroll
            for (int ni = 0; ni < 4; ni++) {
                const int col = bn + wn * 32 + ni * 8 + tcol;
                float o0 = acc[mi][ni][half * 2 + 0] + bias[col];
                float o1 = acc[mi][ni][half * 2 + 1] + bias[col + 1];
                if (MODE == 1) {
                    const float* rp = resid + (size_t)row * N + col;
                    o0 += rp[0]; o1 += rp[1];
                }
                if (MODE == 2) {
                    o0 = 0.5f * o0 * (1.0f + erff(o0 * 0.70710678118654752f));
                    o1 = 0.5f * o1 * (1.0f + erff(o1 * 0.70710678118654752f));
                    *(uint32_t*)(Oh + packed_idx(row, col, M)) = hi_pair(o0, o1);
                } else if (MODE == 3) {
                    *(uint32_t*)(Oh + (size_t)row * N + col) = hi_pair(o0, o1);
                } else {
                    *(float2*)(C + (size_t)row * N + col) = make_float2(o0, o1);
                }
            }
        }
    }
}

// ---------------- pack fp32 [R,K] -> packed swizzled fp16 ----------------------
__global__ __launch_bounds__(256)
void pack_f32(const float* __restrict__ in, __half* __restrict__ out, int R, int K)
{
    size_t u = (size_t)blockIdx.x * 256 + threadIdx.x;   // one 16B unit = 8 halves
    size_t total = ((size_t)R * K) >> 3;
    if (u >= total) return;
    const int kunits = K >> 3;
    const int row = (int)(u / kunits);
    const int uk  = (int)(u % kunits);
    const int ki = uk >> 3, kc = uk & 7;
    const float4* p = (const float4*)(in + (size_t)row * K + ((size_t)uk << 3));
    float4 v0 = p[0], v1 = p[1];
    uint4 pk;
    pk.x = hi_pair(v0.x, v0.y);
    pk.y = hi_pair(v0.z, v0.w);
    pk.z = hi_pair(v1.x, v1.y);
    pk.w = hi_pair(v1.z, v1.w);
    size_t dst = (((size_t)ki * R + row) << 6) + (size_t)((kc ^ (row & 7)) << 3);
    *(uint4*)(out + dst) = pk;
}

// ---------------- tensor-core attention: one block per (b,h), 4 warps ---------
#define ATT_STRIDE 72   // halves per smem row (144B: conflict-free ldmatrix)
#define ATT_SMEM (3 * 64 * ATT_STRIDE * 2)

__global__ __launch_bounds__(128)
void attn_kernel(const __half* __restrict__ qkvh,
                 const float* __restrict__ rel_bias,
                 __half* __restrict__ cpk, int boff)
{
    extern __shared__ __align__(16) __half smh[];
    __half* Qh = smh;                       // [64][72] row=query, col=d
    __half* Kh = smh + 64 * ATT_STRIDE;     // [64][72] row=key,   col=d
    __half* Vt = smh + 2 * 64 * ATT_STRIDE; // [64][72] row=d,     col=key (transposed)

    const int bh = blockIdx.x;
    const int b = boff + (bh >> 4), h = bh & 15;
    const int tid = threadIdx.x;
    const int wid = tid >> 5, lane = tid & 31;

    const __half* base = qkvh + (size_t)b * SS * (3 * DD) + h * HD;
    for (int i = tid; i < 512; i += 128) {              // 512 8-half chunks
        int r = i >> 3, c8 = (i & 7) << 3;
        const __half* row = base + (size_t)r * (3 * DD);
        *(uint4*)(Qh + r * ATT_STRIDE + c8) = *(const uint4*)(row + c8);
        *(uint4*)(Kh + r * ATT_STRIDE + c8) = *(const uint4*)(row + DD + c8);
        uint4 vv = *(const uint4*)(row + 2 * DD + c8);
        const __half* vh = (const __half*)&vv;
#pragma unroll
        for (int j = 0; j < 8; j++)
            Vt[(c8 + j) * ATT_STRIDE + r] = vh[j];
    }
    __syncthreads();

    const uint32_t qb = smem_u32(Qh), kb = smem_u32(Kh), vb = smem_u32(Vt);
    const int a_r  = lane & 15, a_u = lane >> 4;
    const int b_rr = lane & 7, b_nn = (lane >> 4) & 1, b_u = (lane >> 3) & 1;

    float sacc[8][4];
#pragma unroll
    for (int n = 0; n < 8; n++)
#pragma unroll
        for (int f = 0; f < 4; f++) sacc[n][f] = 0.f;

#pragma unroll
    for (int kt = 0; kt < 4; kt++) {
        uint32_t af[4];
        ldsm4(af, qb + (uint32_t)(((wid * 16 + a_r) * ATT_STRIDE + kt * 16 + a_u * 8) * 2));
#pragma unroll
        for (int jp = 0; jp < 4; jp++) {
            uint32_t bf[4];
            ldsm4(bf, kb + (uint32_t)(((jp * 16 + b_nn * 8 + b_rr) * ATT_STRIDE + kt * 16 + b_u * 8) * 2));
            mma_f16(sacc[2 * jp],     af, bf);
            mma_f16(sacc[2 * jp + 1], af, bf + 2);
        }
    }

    const int trow = lane >> 2, tcol = (lane & 3) * 2;
    const int row0 = wid * 16 + trow;
    const float* br0 = rel_bias + ((size_t)h * SS + row0) * SS;
    const float* br1 = br0 + 8 * SS;
    float m0 = -1e30f, m1 = -1e30f;
#pragma unroll
    for (int n = 0; n < 8; n++) {
        const int c = n * 8 + tcol;
        sacc[n][0] = sacc[n][0] * 0.125f + br0[c];
        sacc[n][1] = sacc[n][1] * 0.125f + br0[c + 1];
        sacc[n][2] = sacc[n][2] * 0.125f + br1[c];
        sacc[n][3] = sacc[n][3] * 0.125f + br1[c + 1];
        m0 = fmaxf(m0, fmaxf(sacc[n][0], sacc[n][1]));
        m1 = fmaxf(m1, fmaxf(sacc[n][2], sacc[n][3]));
    }
    m0 = fmaxf(m0, __shfl_xor_sync(0xffffffffu, m0, 1));
    m0 = fmaxf(m0, __shfl_xor_sync(0xffffffffu, m0, 2));
    m1 = fmaxf(m1, __shfl_xor_sync(0xffffffffu, m1, 1));
    m1 = fmaxf(m1, __shfl_xor_sync(0xffffffffu, m1, 2));

    float s0 = 0.f, s1 = 0.f;
#pragma unroll
    for (int n = 0; n < 8; n++) {
        sacc[n][0] = expf(sacc[n][0] - m0); s0 += sacc[n][0];
        sacc[n][1] = expf(sacc[n][1] - m0); s0 += sacc[n][1];
        sacc[n][2] = expf(sacc[n][2] - m1); s1 += sacc[n][2];
        sacc[n][3] = expf(sacc[n][3] - m1); s1 += sacc[n][3];
    }
    s0 += __shfl_xor_sync(0xffffffffu, s0, 1);
    s0 += __shfl_xor_sync(0xffffffffu, s0, 2);
    s1 += __shfl_xor_sync(0xffffffffu, s1, 1);
    s1 += __shfl_xor_sync(0xffffffffu, s1, 2);
    const float i0 = 1.f / s0, i1 = 1.f / s1;

    uint32_t pa[4][4];
#pragma unroll
    for (int kt = 0; kt < 4; kt++) {
        pa[kt][0] = hi_pair(sacc[2 * kt][0] * i0,     sacc[2 * kt][1] * i0);
        pa[kt][1] = hi_pair(sacc[2 * kt][2] * i1,     sacc[2 * kt][3] * i1);
        pa[kt][2] = hi_pair(sacc[2 * kt + 1][0] * i0, sacc[2 * kt + 1][1] * i0);
        pa[kt][3] = hi_pair(sacc[2 * kt + 1][2] * i1, sacc[2 * kt + 1][3] * i1);
    }

    float oc[8][4];
#pragma unroll
    for (int n = 0; n < 8; n++)
#pragma unroll
        for (int f = 0; f < 4; f++) oc[n][f] = 0.f;

#pragma unroll
    for (int kt = 0; kt < 4; kt++) {
#pragma unroll
        for (int jp = 0; jp < 4; jp++) {
            uint32_t bf[4];
            ldsm4(bf, vb + (uint32_t)(((jp * 16 + b_nn * 8 + b_rr) * ATT_STRIDE + kt * 16 + b_u * 8) * 2));
            mma_f16(oc[2 * jp],     pa[kt], bf);
            mma_f16(oc[2 * jp + 1], pa[kt], bf + 2);
        }
    }

    const int orow0 = b * SS + row0;
#pragma unroll
    for (int n = 0; n < 8; n++) {
        const int col = h * HD + n * 8 + tcol;
        *(uint32_t*)(cpk + packed_idx(orow0,     col, MM)) = hi_pair(oc[n][0], oc[n][1]);
        *(uint32_t*)(cpk + packed_idx(orow0 + 8, col, MM)) = hi_pair(oc[n][2], oc[n][3]);
    }
}

// ---------------- layernorm over D=1024, one block per row -------------------
template <int PAIR>
__global__ __launch_bounds__(256)
void ln_kernel(const float* __restrict__ x, const float* __restrict__ gamma,
               const float* __restrict__ beta, float* __restrict__ out,
               __half* __restrict__ opk, int moff)
{
    const int row = moff + blockIdx.x;
    const int tid = threadIdx.x;
    const float* xr = x + (size_t)row * DD;
    float4 vv = ((const float4*)xr)[tid];
    float sm = vv.x + vv.y + vv.z + vv.w;
    float sq = vv.x * vv.x + vv.y * vv.y + vv.z * vv.z + vv.w * vv.w;
#pragma unroll
    for (int o = 16; o > 0; o >>= 1) {
        sm += __shfl_xor_sync(0xffffffffu, sm, o);
        sq += __shfl_xor_sync(0xffffffffu, sq, o);
    }
    __shared__ float s1[8], s2[8];
    if ((tid & 31) == 0) { s1[tid >> 5] = sm; s2[tid >> 5] = sq; }
    __syncthreads();
    float ts = 0.f, tq = 0.f;
#pragma unroll
    for (int i = 0; i < 8; i++) { ts += s1[i]; tq += s2[i]; }
    const float mean = ts * (1.0f / DD);
    const float var  = tq * (1.0f / DD) - mean * mean;
    const float inv  = rsqrtf(var + 1e-5f);
    float4 g4 = ((const float4*)gamma)[tid];
    float4 b4 = ((const float4*)beta)[tid];
    float4 o4;
    o4.x = (vv.x - mean) * inv * g4.x + b4.x;
    o4.y = (vv.y - mean) * inv * g4.y + b4.y;
    o4.z = (vv.z - mean) * inv * g4.z + b4.z;
    o4.w = (vv.w - mean) * inv * g4.w + b4.w;
    ((float4*)(out + (size_t)row * DD))[tid] = o4;
    if (PAIR) {
        uint2 hv;
        hv.x = hi_pair(o4.x, o4.y);
        hv.y = hi_pair(o4.z, o4.w);
        *(uint2*)(opk + packed_idx(row, tid * 4, MM)) = hv;
    }
}

// ---------------- launcher ----------------------------------------------------
extern "C" void kernel_launch(void* const* d_in, const int* in_sizes, int n_in,
                              void* d_out, int out_size)
{
    const float* x        = (const float*)d_in[0];
    const float* w_in     = (const float*)d_in[1];
    const float* b_in     = (const float*)d_in[2];
    const float* w_out    = (const float*)d_in[3];
    const float* b_out    = (const float*)d_in[4];
    const float* rel_bias = (const float*)d_in[5];
    const float* g1       = (const float*)d_in[6];
    const float* be1      = (const float*)d_in[7];
    const float* w1       = (const float*)d_in[8];
    const float* b1       = (const float*)d_in[9];
    const float* w2       = (const float*)d_in[10];
    const float* b2       = (const float*)d_in[11];
    const float* g2       = (const float*)d_in[12];
    const float* be2      = (const float*)d_in[13];
    float* out            = (float*)d_out;

    float *res1, *ln1, *res2;
    __half *qkvh;
    cudaGetSymbolAddress((void**)&qkvh, g_qkvh);
    cudaGetSymbolAddress((void**)&res1, g_res1);
    cudaGetSymbolAddress((void**)&ln1,  g_ln1);
    cudaGetSymbolAddress((void**)&res2, g_res2);

    __half *xpk, *wipk, *wopk, *w1pk, *w2pk, *cpk, *l1pk, *hpk;
    cudaGetSymbolAddress((void**)&xpk,  g_xpk);
    cudaGetSymbolAddress((void**)&wipk, g_wipk);
    cudaGetSymbolAddress((void**)&wopk, g_wopk);
    cudaGetSymbolAddress((void**)&w1pk, g_w1pk);
    cudaGetSymbolAddress((void**)&w2pk, g_w2pk);
    cudaGetSymbolAddress((void**)&cpk,  g_cpk);
    cudaGetSymbolAddress((void**)&l1pk, g_l1pk);
    cudaGetSymbolAddress((void**)&hpk,  g_hpk);

    cudaFuncSetAttribute(attn_kernel, cudaFuncAttributeMaxDynamicSharedMemorySize, ATT_SMEM);
    cudaFuncSetAttribute(tcgemm<0>, cudaFuncAttributeMaxDynamicSharedMemorySize, GEMM_SMEM);
    cudaFuncSetAttribute(tcgemm<1>, cudaFuncAttributeMaxDynamicSharedMemorySize, GEMM_SMEM);
    cudaFuncSetAttribute(tcgemm<2>, cudaFuncAttributeMaxDynamicSharedMemorySize, GEMM_SMEM);
    cudaFuncSetAttribute(tcgemm<3>, cudaFuncAttributeMaxDynamicSharedMemorySize, GEMM_SMEM);

    dim3 blk(256);
    dim3 gblk(512);

    // streams/events from static-init pack (no creation in this function)
    const bool fork = g_sp.ok;
    cudaStream_t sH[2];
    sH[0] = fork ? g_sp.s0 : 0;
    sH[1] = fork ? g_sp.s1 : 0;

    // ---- critical-path packs on origin stream: wi + x
    pack_f32<<<(3 * DD * DD / 8 + 255) / 256, blk>>>(w_in, wipk, 3 * DD, DD);
    pack_f32<<<(MM * DD / 8 + 255) / 256, blk>>>(x, xpk, MM, DD);
    if (fork) {
        cudaEventRecord(g_sp.eW, 0);
        cudaStreamWaitEvent(sH[0], g_sp.eW, 0);
        cudaStreamWaitEvent(sH[1], g_sp.eW, 0);
    }

    // ---- per-half: QKV (fp16 out) + attention
    for (int h = 0; h < 2; h++) {
        const int mo = h * MHALF, bo = h * BHALF;
        tcgemm<3><<<dim3(3 * DD / 128, MHALF / 256), gblk, GEMM_SMEM, sH[h]>>>(
            xpk, wipk, b_in, nullptr, nullptr, qkvh, MM, 3 * DD, DD, mo);
        attn_kernel<<<BHALF * HH, 128, ATT_SMEM, sH[h]>>>(qkvh, rel_bias, cpk, bo);
    }

    // ---- late weight packs on origin stream (overlap with QKV/attn halves)
    pack_f32<<<(DD * DD / 8 + 255) / 256, blk>>>(w_out, wopk, DD, DD);
    pack_f32<<<(FFN_ * DD / 8 + 255) / 256, blk>>>(w1, w1pk, FFN_, DD);
    pack_f32<<<(DD * FFN_ / 8 + 255) / 256, blk>>>(w2, w2pk, DD, FFN_);
    if (fork) {
        cudaEventRecord(g_sp.eW2, 0);
        cudaStreamWaitEvent(sH[0], g_sp.eW2, 0);
        cudaStreamWaitEvent(sH[1], g_sp.eW2, 0);
    }

    // ---- per-half: out-proj -> LN1 -> FFN1 -> FFN2 -> LN2
    for (int h = 0; h < 2; h++) {
        const int mo = h * MHALF;
        tcgemm<1><<<dim3(DD / 128, MHALF / 256), gblk, GEMM_SMEM, sH[h]>>>(
            cpk, wopk, b_out, x, res1, nullptr, MM, DD, DD, mo);
        ln_kernel<1><<<MHALF, blk, 0, sH[h]>>>(res1, g1, be1, ln1, l1pk, mo);
        tcgemm<2><<<dim3(FFN_ / 128, MHALF / 256), gblk, GEMM_SMEM, sH[h]>>>(
            l1pk, w1pk, b1, nullptr, nullptr, hpk, MM, FFN_, DD, mo);
        tcgemm<1><<<dim3(DD / 128, MHALF / 256), gblk, GEMM_SMEM, sH[h]>>>(
            hpk, w2pk, b2, ln1, res2, nullptr, MM, DD, FFN_, mo);
        ln_kernel<0><<<MHALF, blk, 0, sH[h]>>>(res2, g2, be2, out, nullptr, mo);
    }

    // ---- join both halves back into the origin stream
    if (fork) {
        cudaEventRecord(g_sp.eJ0, sH[0]);
        cudaEventRecord(g_sp.eJ1, sH[1]);
        cudaStreamWaitEvent(0, g_sp.eJ0, 0);
        cudaStreamWaitEvent(0, g_sp.eJ1, 0);
    }
}

// round 17
// speedup vs baseline: 1.0715x; 1.0715x over previous
#include <cuda_runtime.h>
#include <cuda_fp16.h>
#include <math.h>
#include <stdint.h>

// Problem dims
#define BB   128
#define SS   64
#define DD   1024
#define HH   16
#define HD   64
#define FFN_ 4096
#define MM   (BB*SS)   // 8192 tokens
#define MHALF (MM/2)   // 4096 rows per half-pipeline
#define BHALF (BB/2)

// ---------------- scratch (device globals; no allocation allowed) ------------
__device__ __align__(128) __half g_qkvh[(size_t)MM * 3 * DD];  // [M, 3D] fp16
__device__ __align__(128) __half g_d1[(size_t)MM * DD];        // out-proj delta fp16
__device__ __align__(128) __half g_d2[(size_t)MM * DD];        // FFN2 delta fp16
__device__ __align__(128) float g_ln1[(size_t)MM * DD];

// packed fp16 operand buffers: layout [ki][row][64] halves, swizzle baked in
__device__ __align__(128) __half g_xpk[(size_t)MM * DD];
__device__ __align__(128) __half g_wipk[(size_t)3 * DD * DD];
__device__ __align__(128) __half g_wopk[(size_t)DD * DD];
__device__ __align__(128) __half g_w1pk[(size_t)FFN_ * DD];
__device__ __align__(128) __half g_w2pk[(size_t)DD * FFN_];
__device__ __align__(128) __half g_cpk[(size_t)MM * DD];
__device__ __align__(128) __half g_l1pk[(size_t)MM * DD];
__device__ __align__(128) __half g_hpk[(size_t)MM * FFN_];

// ---------------- stream pack: created ONCE at static init (pre-main, pre-baseline)
struct StreamPack {
    cudaStream_t s0, s1;
    cudaEvent_t  eW, eW2, eJ0, eJ1;
    bool ok;
    StreamPack() : s0(0), s1(0), eW(0), eW2(0), eJ0(0), eJ1(0), ok(false) {
        ok = cudaStreamCreateWithFlags(&s0, cudaStreamNonBlocking) == cudaSuccess &&
             cudaStreamCreateWithFlags(&s1, cudaStreamNonBlocking) == cudaSuccess &&
             cudaEventCreateWithFlags(&eW,  cudaEventDisableTiming) == cudaSuccess &&
             cudaEventCreateWithFlags(&eW2, cudaEventDisableTiming) == cudaSuccess &&
             cudaEventCreateWithFlags(&eJ0, cudaEventDisableTiming) == cudaSuccess &&
             cudaEventCreateWithFlags(&eJ1, cudaEventDisableTiming) == cudaSuccess;
        if (!ok) { s0 = 0; s1 = 0; }
    }
};
static StreamPack g_sp;   // constructed at load time, before main()

// ---------------- helpers ------------------------------------------------------
__device__ __forceinline__ uint32_t smem_u32(const void* p) {
    return (uint32_t)__cvta_generic_to_shared(p);
}

__device__ __forceinline__ void ldsm4(uint32_t* r, uint32_t addr) {
    asm volatile("ldmatrix.sync.aligned.m8n8.x4.shared.b16 {%0,%1,%2,%3}, [%4];\n"
                 : "=r"(r[0]), "=r"(r[1]), "=r"(r[2]), "=r"(r[3]) : "r"(addr));
}

__device__ __forceinline__ void mma_f16(float* d, const uint32_t* a, const uint32_t* b) {
    asm volatile(
        "mma.sync.aligned.m16n8k16.row.col.f32.f16.f16.f32 "
        "{%0,%1,%2,%3}, {%4,%5,%6,%7}, {%8,%9}, {%0,%1,%2,%3};\n"
        : "+f"(d[0]), "+f"(d[1]), "+f"(d[2]), "+f"(d[3])
        : "r"(a[0]), "r"(a[1]), "r"(a[2]), "r"(a[3]), "r"(b[0]), "r"(b[1]));
}

__device__ __forceinline__ void mbar_init(uint32_t mbar, uint32_t cnt) {
    asm volatile("mbarrier.init.shared.b64 [%0], %1;" :: "r"(mbar), "r"(cnt) : "memory");
}
__device__ __forceinline__ void mbar_expect_tx(uint32_t mbar, uint32_t bytes) {
    asm volatile("mbarrier.arrive.expect_tx.shared.b64 _, [%0], %1;"
                 :: "r"(mbar), "r"(bytes) : "memory");
}
__device__ __forceinline__ void mbar_arrive(uint32_t mbar) {
    asm volatile("mbarrier.arrive.shared.b64 _, [%0];" :: "r"(mbar) : "memory");
}
__device__ __forceinline__ void mbar_wait(uint32_t mbar, uint32_t parity) {
    asm volatile(
        "{\n\t.reg .pred P1;\n\t"
        "WL_%=:\n\t"
        "mbarrier.try_wait.parity.acquire.cta.shared::cta.b64 P1, [%0], %1, 0x989680;\n\t"
        "@P1 bra.uni WD_%=;\n\t"
        "bra.uni WL_%=;\n\t"
        "WD_%=:\n\t}"
        :: "r"(mbar), "r"(parity) : "memory");
}
__device__ __forceinline__ void bulk_g2s(uint32_t dst, const void* src, uint32_t bytes, uint32_t mbar) {
    asm volatile(
        "cp.async.bulk.shared::cluster.global.mbarrier::complete_tx::bytes [%0], [%1], %2, [%3];"
        :: "r"(dst), "l"(src), "r"(bytes), "r"(mbar) : "memory");
}

__device__ __forceinline__ uint32_t pack_h2(__half a, __half b) {
    return ((uint32_t)*(uint16_t*)&b << 16) | (uint32_t)*(uint16_t*)&a;
}
__device__ __forceinline__ uint32_t hi_pair(float a, float b) {
    return pack_h2(__float2half_rn(a), __float2half_rn(b));
}

// packed index: matrix [R rows, K cols] fp16 -> [ki][row][64] with unit swizzle
__device__ __forceinline__ size_t packed_idx(int row, int col, int R) {
    int kc = (col >> 3) & 7;
    return (((size_t)(col >> 6) * (size_t)R + (size_t)row) << 6)
         + (size_t)(((kc ^ (row & 7)) << 3) + (col & 7));
}

// ---------------- bulk-async fp16 GEMM, full/empty mbarrier pipeline -----------
// MODE 0: C = acc + bias (fp32); MODE 2: gelu(acc+bias) -> packed fp16 (Oh);
// MODE 3: acc + bias -> plain fp16 row-major (Oh).
// CTA tile 128x128, KC=64, 256 threads (8 warps 2x4), 3-stage ring, 2 CTAs/SM.
#define A_BYTES 16384                 // 128 rows x 128B
#define B_BYTES 16384                 // 128 rows x 128B
#define STAGE   (A_BYTES + B_BYTES)   // 32768
#define NSTAGE 3
#define GEMM_SMEM (NSTAGE * STAGE)    // 98304
#define NWARPS 8

template <int MODE>
__global__ void __launch_bounds__(256, 2)
tcgemm(const __half* __restrict__ Apk, const __half* __restrict__ Bpk,
       const float* __restrict__ bias,
       float* __restrict__ C, __half* __restrict__ Oh,
       int M, int N, int K, int mo)
{
    extern __shared__ __align__(128) char smem[];
    __shared__ __align__(8) uint64_t full_s[NSTAGE];
    __shared__ __align__(8) uint64_t empty_s[NSTAGE];
    const uint32_t sb = smem_u32(smem);
    const uint32_t fb = smem_u32(full_s);
    const uint32_t eb = smem_u32(empty_s);

    const int tid  = threadIdx.x;
    const int wid  = tid >> 5;
    const int lane = tid & 31;
    const int wm   = wid >> 2;        // 0..1 (64 rows each)
    const int wn   = wid & 3;         // 0..3 (32 cols each)
    const int bn   = blockIdx.x * 128;
    const int bm   = mo + blockIdx.y * 128;
    const int T    = K >> 6;
    const bool producer = (wid == NWARPS - 1) && (lane == 0);

    float acc[4][4][4];
#pragma unroll
    for (int i = 0; i < 4; i++)
#pragma unroll
        for (int j = 0; j < 4; j++)
#pragma unroll
            for (int f = 0; f < 4; f++) acc[i][j][f] = 0.f;

    if (tid == 0) {
#pragma unroll
        for (int s = 0; s < NSTAGE; s++) {
            mbar_init(fb + 8 * s, 1);
            mbar_init(eb + 8 * s, NWARPS);
        }
        asm volatile("fence.proxy.async.shared::cta;" ::: "memory");
    }
    __syncthreads();

    if (producer) {
#pragma unroll
        for (int s = 0; s < NSTAGE; s++) {
            mbar_expect_tx(fb + 8 * s, STAGE);
            bulk_g2s(sb + s * STAGE,           Apk + (((size_t)s * M + bm) << 6), A_BYTES, fb + 8 * s);
            bulk_g2s(sb + s * STAGE + A_BYTES, Bpk + (((size_t)s * N + bn) << 6), B_BYTES, fb + 8 * s);
        }
    }

    const int a_r  = lane & 15;
    const int a_u  = lane >> 4;
    const int b_rr = lane & 7;
    const int b_nn = (lane >> 4) & 1;
    const int b_u  = (lane >> 3) & 1;

    int slot = 0;
    uint32_t ph = 0;
    for (int t = 0; t < T; ++t) {
        mbar_wait(fb + 8 * slot, ph);
        const uint32_t stA = sb + slot * STAGE;
        const uint32_t stB = stA + A_BYTES;
#pragma unroll
        for (int ks = 0; ks < 4; ks++) {
            uint32_t ah[4][4];
#pragma unroll
            for (int mi = 0; mi < 4; mi++) {
                int r = wm * 64 + mi * 16 + a_r;
                int u = ks * 2 + a_u;
                ldsm4(ah[mi], stA + (uint32_t)(r * 128 + ((u ^ (r & 7)) << 4)));
            }
#pragma unroll
            for (int jp = 0; jp < 2; jp++) {
                int r = wn * 32 + jp * 16 + b_nn * 8 + b_rr;
                int u = ks * 2 + b_u;
                uint32_t bf[4];
                ldsm4(bf, stB + (uint32_t)(r * 128 + ((u ^ (r & 7)) << 4)));
#pragma unroll
                for (int mi = 0; mi < 4; mi++) {
                    mma_f16(acc[mi][2 * jp],     ah[mi], bf);
                    mma_f16(acc[mi][2 * jp + 1], ah[mi], bf + 2);
                }
            }
        }
        if (lane == 0) mbar_arrive(eb + 8 * slot);
        if (producer && t + NSTAGE < T) {
            mbar_wait(eb + 8 * slot, ph);
            const int kk = t + NSTAGE;
            mbar_expect_tx(fb + 8 * slot, STAGE);
            bulk_g2s(sb + slot * STAGE,           Apk + (((size_t)kk * M + bm) << 6), A_BYTES, fb + 8 * slot);
            bulk_g2s(sb + slot * STAGE + A_BYTES, Bpk + (((size_t)kk * N + bn) << 6), B_BYTES, fb + 8 * slot);
        }
        if (++slot == NSTAGE) { slot = 0; ph ^= 1; }
    }

    // ---------------- epilogue (register-only) --------------------------------
    const int trow = lane >> 2;
    const int tcol = (lane & 3) * 2;
#pragma unroll
    for (int mi = 0; mi < 4; mi++) {
#pragma unroll
        for (int half = 0; half < 2; half++) {
            const int row = bm + wm * 64 + mi * 16 + trow + half * 8;
#pragma unroll
            for (int ni = 0; ni < 4; ni++) {
                const int col = bn + wn * 32 + ni * 8 + tcol;
                float o0 = acc[mi][ni][half * 2 + 0] + bias[col];
                float o1 = acc[mi][ni][half * 2 + 1] + bias[col + 1];
                if (MODE == 2) {
                    o0 = 0.5f * o0 * (1.0f + erff(o0 * 0.70710678118654752f));
                    o1 = 0.5f * o1 * (1.0f + erff(o1 * 0.70710678118654752f));
                    *(uint32_t*)(Oh + packed_idx(row, col, M)) = hi_pair(o0, o1);
                } else if (MODE == 3) {
                    *(uint32_t*)(Oh + (size_t)row * N + col) = hi_pair(o0, o1);
                } else {
                    *(float2*)(C + (size_t)row * N + col) = make_float2(o0, o1);
                }
            }
        }
    }
}

// ---------------- pack fp32 [R,K] -> packed swizzled fp16 ----------------------
__global__ __launch_bounds__(256)
void pack_f32(const float* __restrict__ in, __half* __restrict__ out, int R, int K)
{
    size_t u = (size_t)blockIdx.x * 256 + threadIdx.x;   // one 16B unit = 8 halves
    size_t total = ((size_t)R * K) >> 3;
    if (u >= total) return;
    const int kunits = K >> 3;
    const int row = (int)(u / kunits);
    const int uk  = (int)(u % kunits);
    const int ki = uk >> 3, kc = uk & 7;
    const float4* p = (const float4*)(in + (size_t)row * K + ((size_t)uk << 3));
    float4 v0 = p[0], v1 = p[1];
    uint4 pk;
    pk.x = hi_pair(v0.x, v0.y);
    pk.y = hi_pair(v0.z, v0.w);
    pk.z = hi_pair(v1.x, v1.y);
    pk.w = hi_pair(v1.z, v1.w);
    size_t dst = (((size_t)ki * R + row) << 6) + (size_t)((kc ^ (row & 7)) << 3);
    *(uint4*)(out + dst) = pk;
}

// ---------------- tensor-core attention: one block per (b,h), 4 warps ---------
#define ATT_STRIDE 72   // halves per smem row (144B: conflict-free ldmatrix)
#define ATT_SMEM (3 * 64 * ATT_STRIDE * 2)

__global__ __launch_bounds__(128)
void attn_kernel(const __half* __restrict__ qkvh,
                 const float* __restrict__ rel_bias,
                 __half* __restrict__ cpk, int boff)
{
    extern __shared__ __align__(16) __half smh[];
    __half* Qh = smh;                       // [64][72] row=query, col=d
    __half* Kh = smh + 64 * ATT_STRIDE;     // [64][72] row=key,   col=d
    __half* Vt = smh + 2 * 64 * ATT_STRIDE; // [64][72] row=d,     col=key (transposed)

    const int bh = blockIdx.x;
    const int b = boff + (bh >> 4), h = bh & 15;
    const int tid = threadIdx.x;
    const int wid = tid >> 5, lane = tid & 31;

    const __half* base = qkvh + (size_t)b * SS * (3 * DD) + h * HD;
    for (int i = tid; i < 512; i += 128) {              // 512 8-half chunks
        int r = i >> 3, c8 = (i & 7) << 3;
        const __half* row = base + (size_t)r * (3 * DD);
        *(uint4*)(Qh + r * ATT_STRIDE + c8) = *(const uint4*)(row + c8);
        *(uint4*)(Kh + r * ATT_STRIDE + c8) = *(const uint4*)(row + DD + c8);
        uint4 vv = *(const uint4*)(row + 2 * DD + c8);
        const __half* vh = (const __half*)&vv;
#pragma unroll
        for (int j = 0; j < 8; j++)
            Vt[(c8 + j) * ATT_STRIDE + r] = vh[j];
    }
    __syncthreads();

    const uint32_t qb = smem_u32(Qh), kb = smem_u32(Kh), vb = smem_u32(Vt);
    const int a_r  = lane & 15, a_u = lane >> 4;
    const int b_rr = lane & 7, b_nn = (lane >> 4) & 1, b_u = (lane >> 3) & 1;

    float sacc[8][4];
#pragma unroll
    for (int n = 0; n < 8; n++)
#pragma unroll
        for (int f = 0; f < 4; f++) sacc[n][f] = 0.f;

#pragma unroll
    for (int kt = 0; kt < 4; kt++) {
        uint32_t af[4];
        ldsm4(af, qb + (uint32_t)(((wid * 16 + a_r) * ATT_STRIDE + kt * 16 + a_u * 8) * 2));
#pragma unroll
        for (int jp = 0; jp < 4; jp++) {
            uint32_t bf[4];
            ldsm4(bf, kb + (uint32_t)(((jp * 16 + b_nn * 8 + b_rr) * ATT_STRIDE + kt * 16 + b_u * 8) * 2));
            mma_f16(sacc[2 * jp],     af, bf);
            mma_f16(sacc[2 * jp + 1], af, bf + 2);
        }
    }

    const int trow = lane >> 2, tcol = (lane & 3) * 2;
    const int row0 = wid * 16 + trow;
    const float* br0 = rel_bias + ((size_t)h * SS + row0) * SS;
    const float* br1 = br0 + 8 * SS;
    float m0 = -1e30f, m1 = -1e30f;
#pragma unroll
    for (int n = 0; n < 8; n++) {
        const int c = n * 8 + tcol;
        sacc[n][0] = sacc[n][0] * 0.125f + br0[c];
        sacc[n][1] = sacc[n][1] * 0.125f + br0[c + 1];
        sacc[n][2] = sacc[n][2] * 0.125f + br1[c];
        sacc[n][3] = sacc[n][3] * 0.125f + br1[c + 1];
        m0 = fmaxf(m0, fmaxf(sacc[n][0], sacc[n][1]));
        m1 = fmaxf(m1, fmaxf(sacc[n][2], sacc[n][3]));
    }
    m0 = fmaxf(m0, __shfl_xor_sync(0xffffffffu, m0, 1));
    m0 = fmaxf(m0, __shfl_xor_sync(0xffffffffu, m0, 2));
    m1 = fmaxf(m1, __shfl_xor_sync(0xffffffffu, m1, 1));
    m1 = fmaxf(m1, __shfl_xor_sync(0xffffffffu, m1, 2));

    float s0 = 0.f, s1 = 0.f;
#pragma unroll
    for (int n = 0; n < 8; n++) {
        sacc[n][0] = expf(sacc[n][0] - m0); s0 += sacc[n][0];
        sacc[n][1] = expf(sacc[n][1] - m0); s0 += sacc[n][1];
        sacc[n][2] = expf(sacc[n][2] - m1); s1 += sacc[n][2];
        sacc[n][3] = expf(sacc[n][3] - m1); s1 += sacc[n][3];
    }
    s0 += __shfl_xor_sync(0xffffffffu, s0, 1);
    s0 += __shfl_xor_sync(0xffffffffu, s0, 2);
    s1 += __shfl_xor_sync(0xffffffffu, s1, 1);
    s1 += __shfl_xor_sync(0xffffffffu, s1, 2);
    const float i0 = 1.f / s0, i1 = 1.f / s1;

    uint32_t pa[4][4];
#pragma unroll
    for (int kt = 0; kt < 4; kt++) {
        pa[kt][0] = hi_pair(sacc[2 * kt][0] * i0,     sacc[2 * kt][1] * i0);
        pa[kt][1] = hi_pair(sacc[2 * kt][2] * i1,     sacc[2 * kt][3] * i1);
        pa[kt][2] = hi_pair(sacc[2 * kt + 1][0] * i0, sacc[2 * kt + 1][1] * i0);
        pa[kt][3] = hi_pair(sacc[2 * kt + 1][2] * i1, sacc[2 * kt + 1][3] * i1);
    }

    float oc[8][4];
#pragma unroll
    for (int n = 0; n < 8; n++)
#pragma unroll
        for (int f = 0; f < 4; f++) oc[n][f] = 0.f;

#pragma unroll
    for (int kt = 0; kt < 4; kt++) {
#pragma unroll
        for (int jp = 0; jp < 4; jp++) {
            uint32_t bf[4];
            ldsm4(bf, vb + (uint32_t)(((jp * 16 + b_nn * 8 + b_rr) * ATT_STRIDE + kt * 16 + b_u * 8) * 2));
            mma_f16(oc[2 * jp],     pa[kt], bf);
            mma_f16(oc[2 * jp + 1], pa[kt], bf + 2);
        }
    }

    const int orow0 = b * SS + row0;
#pragma unroll
    for (int n = 0; n < 8; n++) {
        const int col = h * HD + n * 8 + tcol;
        *(uint32_t*)(cpk + packed_idx(orow0,     col, MM)) = hi_pair(oc[n][0], oc[n][1]);
        *(uint32_t*)(cpk + packed_idx(orow0 + 8, col, MM)) = hi_pair(oc[n][2], oc[n][3]);
    }
}

// ---------------- layernorm over D=1024: LN(xsrc + delta) --------------------
// xsrc fp32, delta fp16. PAIR=1: also emit packed fp16 of the output.
template <int PAIR>
__global__ __launch_bounds__(256)
void ln_kernel(const float* __restrict__ xsrc, const __half* __restrict__ delta,
               const float* __restrict__ gamma, const float* __restrict__ beta,
               float* __restrict__ out, __half* __restrict__ opk, int moff)
{
    const int row = moff + blockIdx.x;
    const int tid = threadIdx.x;
    float4 vv = ((const float4*)(xsrc + (size_t)row * DD))[tid];
    uint2 dv = ((const uint2*)(delta + (size_t)row * DD))[tid];
    const __half* dh = (const __half*)&dv;
    vv.x += __half2float(dh[0]);
    vv.y += __half2float(dh[1]);
    vv.z += __half2float(dh[2]);
    vv.w += __half2float(dh[3]);

    float sm = vv.x + vv.y + vv.z + vv.w;
    float sq = vv.x * vv.x + vv.y * vv.y + vv.z * vv.z + vv.w * vv.w;
#pragma unroll
    for (int o = 16; o > 0; o >>= 1) {
        sm += __shfl_xor_sync(0xffffffffu, sm, o);
        sq += __shfl_xor_sync(0xffffffffu, sq, o);
    }
    __shared__ float s1[8], s2[8];
    if ((tid & 31) == 0) { s1[tid >> 5] = sm; s2[tid >> 5] = sq; }
    __syncthreads();
    float ts = 0.f, tq = 0.f;
#pragma unroll
    for (int i = 0; i < 8; i++) { ts += s1[i]; tq += s2[i]; }
    const float mean = ts * (1.0f / DD);
    const float var  = tq * (1.0f / DD) - mean * mean;
    const float inv  = rsqrtf(var + 1e-5f);
    float4 g4 = ((const float4*)gamma)[tid];
    float4 b4 = ((const float4*)beta)[tid];
    float4 o4;
    o4.x = (vv.x - mean) * inv * g4.x + b4.x;
    o4.y = (vv.y - mean) * inv * g4.y + b4.y;
    o4.z = (vv.z - mean) * inv * g4.z + b4.z;
    o4.w = (vv.w - mean) * inv * g4.w + b4.w;
    ((float4*)(out + (size_t)row * DD))[tid] = o4;
    if (PAIR) {
        uint2 hv;
        hv.x = hi_pair(o4.x, o4.y);
        hv.y = hi_pair(o4.z, o4.w);
        *(uint2*)(opk + packed_idx(row, tid * 4, MM)) = hv;
    }
}

// ---------------- launcher ----------------------------------------------------
extern "C" void kernel_launch(void* const* d_in, const int* in_sizes, int n_in,
                              void* d_out, int out_size)
{
    const float* x        = (const float*)d_in[0];
    const float* w_in     = (const float*)d_in[1];
    const float* b_in     = (const float*)d_in[2];
    const float* w_out    = (const float*)d_in[3];
    const float* b_out    = (const float*)d_in[4];
    const float* rel_bias = (const float*)d_in[5];
    const float* g1       = (const float*)d_in[6];
    const float* be1      = (const float*)d_in[7];
    const float* w1       = (const float*)d_in[8];
    const float* b1       = (const float*)d_in[9];
    const float* w2       = (const float*)d_in[10];
    const float* b2       = (const float*)d_in[11];
    const float* g2       = (const float*)d_in[12];
    const float* be2      = (const float*)d_in[13];
    float* out            = (float*)d_out;

    float *ln1;
    __half *qkvh, *d1, *d2;
    cudaGetSymbolAddress((void**)&qkvh, g_qkvh);
    cudaGetSymbolAddress((void**)&d1,   g_d1);
    cudaGetSymbolAddress((void**)&d2,   g_d2);
    cudaGetSymbolAddress((void**)&ln1,  g_ln1);

    __half *xpk, *wipk, *wopk, *w1pk, *w2pk, *cpk, *l1pk, *hpk;
    cudaGetSymbolAddress((void**)&xpk,  g_xpk);
    cudaGetSymbolAddress((void**)&wipk, g_wipk);
    cudaGetSymbolAddress((void**)&wopk, g_wopk);
    cudaGetSymbolAddress((void**)&w1pk, g_w1pk);
    cudaGetSymbolAddress((void**)&w2pk, g_w2pk);
    cudaGetSymbolAddress((void**)&cpk,  g_cpk);
    cudaGetSymbolAddress((void**)&l1pk, g_l1pk);
    cudaGetSymbolAddress((void**)&hpk,  g_hpk);

    cudaFuncSetAttribute(attn_kernel, cudaFuncAttributeMaxDynamicSharedMemorySize, ATT_SMEM);
    cudaFuncSetAttribute(tcgemm<2>, cudaFuncAttributeMaxDynamicSharedMemorySize, GEMM_SMEM);
    cudaFuncSetAttribute(tcgemm<3>, cudaFuncAttributeMaxDynamicSharedMemorySize, GEMM_SMEM);

    dim3 blk(256);

    // streams/events from static-init pack (no creation in this function)
    const bool fork = g_sp.ok;
    cudaStream_t sH[2];
    sH[0] = fork ? g_sp.s0 : 0;
    sH[1] = fork ? g_sp.s1 : 0;

    // ---- critical-path packs on origin stream: wi + x
    pack_f32<<<(3 * DD * DD / 8 + 255) / 256, blk>>>(w_in, wipk, 3 * DD, DD);
    pack_f32<<<(MM * DD / 8 + 255) / 256, blk>>>(x, xpk, MM, DD);
    if (fork) {
        cudaEventRecord(g_sp.eW, 0);
        cudaStreamWaitEvent(sH[0], g_sp.eW, 0);
        cudaStreamWaitEvent(sH[1], g_sp.eW, 0);
    }

    // ---- per-half: QKV (fp16 out) + attention
    for (int h = 0; h < 2; h++) {
        const int mo = h * MHALF, bo = h * BHALF;
        tcgemm<3><<<dim3(3 * DD / 128, MHALF / 128), blk, GEMM_SMEM, sH[h]>>>(
            xpk, wipk, b_in, nullptr, qkvh, MM, 3 * DD, DD, mo);
        attn_kernel<<<BHALF * HH, 128, ATT_SMEM, sH[h]>>>(qkvh, rel_bias, cpk, bo);
    }

    // ---- late weight packs on origin stream (overlap with QKV/attn halves)
    pack_f32<<<(DD * DD / 8 + 255) / 256, blk>>>(w_out, wopk, DD, DD);
    pack_f32<<<(FFN_ * DD / 8 + 255) / 256, blk>>>(w1, w1pk, FFN_, DD);
    pack_f32<<<(DD * FFN_ / 8 + 255) / 256, blk>>>(w2, w2pk, DD, FFN_);
    if (fork) {
        cudaEventRecord(g_sp.eW2, 0);
        cudaStreamWaitEvent(sH[0], g_sp.eW2, 0);
        cudaStreamWaitEvent(sH[1], g_sp.eW2, 0);
    }

    // ---- per-half: out-proj(delta fp16) -> LN1(x+d1) -> FFN1 -> FFN2(delta) -> LN2(ln1+d2)
    for (int h = 0; h < 2; h++) {
        const int mo = h * MHALF;
        tcgemm<3><<<dim3(DD / 128, MHALF / 128), blk, GEMM_SMEM, sH[h]>>>(
            cpk, wopk, b_out, nullptr, d1, MM, DD, DD, mo);
        ln_kernel<1><<<MHALF, blk, 0, sH[h]>>>(x, d1, g1, be1, ln1, l1pk, mo);
        tcgemm<2><<<dim3(FFN_ / 128, MHALF / 128), blk, GEMM_SMEM, sH[h]>>>(
            l1pk, w1pk, b1, nullptr, hpk, MM, FFN_, DD, mo);
        tcgemm<3><<<dim3(DD / 128, MHALF / 128), blk, GEMM_SMEM, sH[h]>>>(
            hpk, w2pk, b2, nullptr, d2, MM, DD, FFN_, mo);
        ln_kernel<0><<<MHALF, blk, 0, sH[h]>>>(ln1, d2, g2, be2, out, nullptr, mo);
    }

    // ---- join both halves back into the origin stream
    if (fork) {
        cudaEventRecord(g_sp.eJ0, sH[0]);
        cudaEventRecord(g_sp.eJ1, sH[1]);
        cudaStreamWaitEvent(0, g_sp.eJ0, 0);
        cudaStreamWaitEvent(0, g_sp.eJ1, 0);
    }
}